// round 5
// baseline (speedup 1.0000x reference)
#include <cuda_runtime.h>

#define BATCH 64
#define NJ 21
#define BJ (BATCH * NJ)        // 1344
#define IMG 256

// w[d] = exp(-d^2 / (2 * 2.5^2)) = exp(-d^2 / 12.5), d = 0..5
__constant__ float c_w[6] = {
    1.0f,
    0.92311634638663580f,   // exp(-0.08)
    0.72614903707369090f,   // exp(-0.32)
    0.48675225595997170f,   // exp(-0.72)
    0.27803730045319410f,   // exp(-1.28)
    0.13533528323661270f    // exp(-2.00)
};

// One block = one quarter of one (batch, joint) 256x256 map: 64 rows.
// 256 threads, each thread writes 16 float4 (lane-contiguous per store).
// Thread 0 computes the fisheye seed for this map in double (matches jnp
// round-half-to-even exactly; avoids trig via cos(phi)=x/rho, sin(phi)=y/rho).
__global__ void __launch_bounds__(256) hm_kernel(float4* __restrict__ out,
                                                 const float* __restrict__ joint) {
    __shared__ int2 s_seed;

    const unsigned blk = blockIdx.x;
    const unsigned bj  = blk >> 2;
    const unsigned q   = blk & 3u;        // quarter: rows q*64 .. q*64+63

    if (threadIdx.x == 0) {
        double x = (double)joint[bj * 3 + 0];
        double y = (double)joint[bj * 3 + 1];
        double z = (double)joint[bj * 3 + 2];
        double rho = sqrt(x * x + y * y);
        double theta = atan2(rho, z);
        double r = 128.0 * theta / 1.5707963267948966;  // RADIUS * theta / (pi/2)
        double cphi, sphi;
        if (rho > 0.0) { cphi = x / rho; sphi = y / rho; }
        else           { cphi = 1.0;     sphi = 0.0;     }
        int sx = (int)rint(128.0 + r * cphi);
        int sy = (int)rint(128.0 + r * sphi);
        sx = min(max(sx, 0), IMG - 1);
        sy = min(max(sy, 0), IMG - 1);
        s_seed = make_int2(sx, sy);
    }
    __syncthreads();
    const int2 s = s_seed;

    const unsigned tid = threadIdx.x;
    const unsigned x0  = (tid & 63u) << 2;      // column of this thread's float4

    // Column weights: invariant across all 16 rows this thread touches.
    float4 wx;
    {
        float* wxp = reinterpret_cast<float*>(&wx);
#pragma unroll
        for (int k = 0; k < 4; k++) {
            int dx  = (int)(x0 + k) - s.x;
            int adx = dx < 0 ? -dx : dx;
            wxp[k] = (adx <= 5) ? c_w[adx] : 0.0f;
        }
    }

    const int    y_first = (int)(q * 64u + (tid >> 6));   // row at k=0; +4 per k
    const size_t base    = (size_t)bj * (IMG * IMG / 4)
                         + (size_t)q * (64 * 64) + tid;
    float4* o = out + base;

#pragma unroll
    for (int k = 0; k < 16; k++) {
        int y   = y_first + k * 4;
        int dy  = y - s.y;
        int ady = dy < 0 ? -dy : dy;
        float wy = (ady <= 5) ? c_w[ady] : 0.0f;
        o[(size_t)k * 256] = make_float4(wy * wx.x, wy * wx.y, wy * wx.z, wy * wx.w);
    }
}

extern "C" void kernel_launch(void* const* d_in, const int* in_sizes, int n_in,
                              void* d_out, int out_size) {
    const float* joint = (const float*)d_in[0];
    // 1344 maps * 4 quarter-blocks = 5376 blocks of 256 threads
    hm_kernel<<<BJ * 4, 256>>>((float4*)d_out, joint);
}

// round 6
// speedup vs baseline: 1.1046x; 1.1046x over previous
#include <cuda_runtime.h>

#define BATCH 64
#define NJ 21
#define BJ (BATCH * NJ)        // 1344
#define IMG 256

// w[d] = exp(-d^2 / (2 * 2.5^2)) = exp(-d^2 / 12.5), d = 0..5
__constant__ float c_w[6] = {
    1.0f,
    0.92311634638663580f,   // exp(-0.08)
    0.72614903707369090f,   // exp(-0.32)
    0.48675225595997170f,   // exp(-0.72)
    0.27803730045319410f,   // exp(-1.28)
    0.13533528323661270f    // exp(-2.00)
};

// One block = one full (batch, joint) 256x256 map.
// 512 threads, each thread writes 32 float4 (lane-contiguous per store,
// 8 consecutive rows = 8 KB contiguous per unrolled step).
// Thread 0 computes the fisheye seed for this map in double (matches jnp
// round-half-to-even exactly; avoids trig via cos(phi)=x/rho, sin(phi)=y/rho).
__global__ void __launch_bounds__(512) hm_kernel(float4* __restrict__ out,
                                                 const float* __restrict__ joint) {
    __shared__ int2 s_seed;

    const unsigned bj = blockIdx.x;

    if (threadIdx.x == 0) {
        double x = (double)joint[bj * 3 + 0];
        double y = (double)joint[bj * 3 + 1];
        double z = (double)joint[bj * 3 + 2];
        double rho = sqrt(x * x + y * y);
        double theta = atan2(rho, z);
        double r = 128.0 * theta / 1.5707963267948966;  // RADIUS * theta / (pi/2)
        double cphi, sphi;
        if (rho > 0.0) { cphi = x / rho; sphi = y / rho; }
        else           { cphi = 1.0;     sphi = 0.0;     }
        int sx = (int)rint(128.0 + r * cphi);
        int sy = (int)rint(128.0 + r * sphi);
        sx = min(max(sx, 0), IMG - 1);
        sy = min(max(sy, 0), IMG - 1);
        s_seed = make_int2(sx, sy);
    }
    __syncthreads();
    const int2 s = s_seed;

    const unsigned tid = threadIdx.x;
    const unsigned x0  = (tid & 63u) << 2;      // column of this thread's float4

    // Column weights: invariant across all 32 rows this thread touches.
    float4 wx;
    {
        float* wxp = reinterpret_cast<float*>(&wx);
#pragma unroll
        for (int k = 0; k < 4; k++) {
            int dx  = (int)(x0 + k) - s.x;
            int adx = dx < 0 ? -dx : dx;
            wxp[k] = (adx <= 5) ? c_w[adx] : 0.0f;
        }
    }

    const int    y_first = (int)(tid >> 6);     // row at k=0; +8 per k
    const size_t base    = (size_t)bj * (IMG * IMG / 4) + tid;
    float4* o = out + base;

#pragma unroll
    for (int k = 0; k < 32; k++) {
        int y   = y_first + k * 8;
        int dy  = y - s.y;
        int ady = dy < 0 ? -dy : dy;
        float wy = (ady <= 5) ? c_w[ady] : 0.0f;
        o[(size_t)k * 512] = make_float4(wy * wx.x, wy * wx.y, wy * wx.z, wy * wx.w);
    }
}

extern "C" void kernel_launch(void* const* d_in, const int* in_sizes, int n_in,
                              void* d_out, int out_size) {
    const float* joint = (const float*)d_in[0];
    // 1344 maps, one block each, 512 threads
    hm_kernel<<<BJ, 512>>>((float4*)d_out, joint);
}

// round 7
// speedup vs baseline: 1.1095x; 1.0044x over previous
#include <cuda_runtime.h>

#define BATCH 64
#define NJ 21
#define BJ (BATCH * NJ)        // 1344
#define IMG 256

// w[d] = exp(-d^2 / (2 * 2.5^2)) = exp(-d^2 / 12.5), d = 0..5
__constant__ float c_w[6] = {
    1.0f,
    0.92311634638663580f,   // exp(-0.08)
    0.72614903707369090f,   // exp(-0.32)
    0.48675225595997170f,   // exp(-0.72)
    0.27803730045319410f,   // exp(-1.28)
    0.13533528323661270f    // exp(-2.00)
};

// One block = one full (batch, joint) 256x256 map.
// 512 threads, each thread writes 32 float4 (lane-contiguous per store,
// 8 KB contiguous per unrolled step). Stores use __stcg (L2 write-back,
// L1 bypass) — pure write stream never re-reads, L1 adds no value.
// Thread 0 computes the fisheye seed for this map in double (matches jnp
// round-half-to-even exactly; avoids trig via cos(phi)=x/rho, sin(phi)=y/rho).
__global__ void __launch_bounds__(512) hm_kernel(float4* __restrict__ out,
                                                 const float* __restrict__ joint) {
    __shared__ int2 s_seed;

    const unsigned bj = blockIdx.x;

    if (threadIdx.x == 0) {
        double x = (double)joint[bj * 3 + 0];
        double y = (double)joint[bj * 3 + 1];
        double z = (double)joint[bj * 3 + 2];
        double rho = sqrt(x * x + y * y);
        double theta = atan2(rho, z);
        double r = 128.0 * theta / 1.5707963267948966;  // RADIUS * theta / (pi/2)
        double cphi, sphi;
        if (rho > 0.0) { cphi = x / rho; sphi = y / rho; }
        else           { cphi = 1.0;     sphi = 0.0;     }
        int sx = (int)rint(128.0 + r * cphi);
        int sy = (int)rint(128.0 + r * sphi);
        sx = min(max(sx, 0), IMG - 1);
        sy = min(max(sy, 0), IMG - 1);
        s_seed = make_int2(sx, sy);
    }
    __syncthreads();
    const int2 s = s_seed;

    const unsigned tid = threadIdx.x;
    const unsigned x0  = (tid & 63u) << 2;      // column of this thread's float4

    // Column weights: invariant across all 32 rows this thread touches.
    float4 wx;
    {
        float* wxp = reinterpret_cast<float*>(&wx);
#pragma unroll
        for (int k = 0; k < 4; k++) {
            int dx  = (int)(x0 + k) - s.x;
            int adx = dx < 0 ? -dx : dx;
            wxp[k] = (adx <= 5) ? c_w[adx] : 0.0f;
        }
    }

    const int    y_first = (int)(tid >> 6);     // row at k=0; +8 per k
    const size_t base    = (size_t)bj * (IMG * IMG / 4) + tid;
    float4* o = out + base;

#pragma unroll
    for (int k = 0; k < 32; k++) {
        int y   = y_first + k * 8;
        int dy  = y - s.y;
        int ady = dy < 0 ? -dy : dy;
        float wy = (ady <= 5) ? c_w[ady] : 0.0f;
        __stcg(o + (size_t)k * 512,
               make_float4(wy * wx.x, wy * wx.y, wy * wx.z, wy * wx.w));
    }
}

extern "C" void kernel_launch(void* const* d_in, const int* in_sizes, int n_in,
                              void* d_out, int out_size) {
    const float* joint = (const float*)d_in[0];
    // 1344 maps, one block each, 512 threads
    hm_kernel<<<BJ, 512>>>((float4*)d_out, joint);
}